// round 1
// baseline (speedup 1.0000x reference)
#include <cuda_runtime.h>
#include <math_constants.h>

#define N_ELEM  16384
#define TI      1024      // i-rows per block
#define TJ      256       // j-cols per block (== THREADS)
#define IPT     4         // i's per thread (TI = THREADS * IPT)
#define THREADS 256

// Global scratch / accumulators (no allocations allowed)
__device__ unsigned int g_cc;
__device__ unsigned int g_tp;
__device__ float        g_ymask[N_ELEM];   // status ? y : +INF

__global__ void cindex_zero_kernel() {
    g_cc = 0u;
    g_tp = 0u;
}

__global__ void cindex_prep_kernel(const float* __restrict__ y,
                                   const int* __restrict__ status) {
    int i = blockIdx.x * blockDim.x + threadIdx.x;
    if (i < N_ELEM) {
        g_ymask[i] = (status[i] == 1) ? y[i] : CUDART_INF_F;
    }
}

// Pairwise kernel over the strict upper triangle (j > i).
// Per pair (i, j):
//   c1  = (y_i  >= y_j) && s_j        == (y_i   >= ymask_j)
//   cc1 = c1 && (yh_i >= yh_j)
//   c2  = (y_i  <= y_j) && s_i        == (ymask_i <= y_j)
//   cc2 = c2 && (yh_i <= yh_j)
//   tp += c1 | c2 ;  cc += cc1 | cc2
__global__ __launch_bounds__(THREADS)
void cindex_pair_kernel(const float* __restrict__ y,
                        const float* __restrict__ yh) {
    const int bi = blockIdx.y;
    const int bj = blockIdx.x;
    const int ibase = bi * TI;
    const int jbase = bj * TJ;

    // No pair with j > i in this tile -> nothing to do.
    if (jbase + TJ - 1 <= ibase) return;

    // Does the tile straddle the diagonal?
    const bool masked = (ibase + TI - 1 >= jbase);

    __shared__ float sy[TJ];
    __shared__ float sym[TJ];
    __shared__ float syh[TJ];

    const int t = threadIdx.x;
    sy[t]  = y[jbase + t];
    sym[t] = g_ymask[jbase + t];
    syh[t] = yh[jbase + t];
    __syncthreads();

    float yi[IPT], ymi[IPT], yhi[IPT];
    int   ig[IPT];
#pragma unroll
    for (int k = 0; k < IPT; k++) {
        const int i = ibase + t + k * THREADS;
        ig[k]  = i;
        yi[k]  = y[i];
        ymi[k] = g_ymask[i];
        yhi[k] = yh[i];
    }

    unsigned int cc = 0u, tp = 0u;

    if (!masked) {
        // Fast path: every (i, j) in tile satisfies j > i.
#pragma unroll 4
        for (int j = 0; j < TJ; j++) {
            const float yj  = sy[j];
            const float ymj = sym[j];
            const float yhj = syh[j];
#pragma unroll
            for (int k = 0; k < IPT; k++) {
                const bool c1  = (yi[k]  >= ymj);
                const bool cc1 = c1 && (yhi[k] >= yhj);
                const bool c2  = (ymi[k] <= yj);
                const bool cc2 = c2 && (yhi[k] <= yhj);
                tp += (unsigned int)(c1 | c2);
                cc += (unsigned int)(cc1 | cc2);
            }
        }
    } else {
        // Diagonal-straddling tiles: add explicit j > i mask.
        for (int j = 0; j < TJ; j++) {
            const float yj  = sy[j];
            const float ymj = sym[j];
            const float yhj = syh[j];
            const int   jg  = jbase + j;
#pragma unroll
            for (int k = 0; k < IPT; k++) {
                const bool m   = (jg > ig[k]);
                const bool c1  = (yi[k]  >= ymj);
                const bool cc1 = c1 && (yhi[k] >= yhj);
                const bool c2  = (ymi[k] <= yj);
                const bool cc2 = c2 && (yhi[k] <= yhj);
                tp += (unsigned int)((c1 | c2) & m);
                cc += (unsigned int)((cc1 | cc2) & m);
            }
        }
    }

    // Warp reduction, then one atomic per warp (integer adds: deterministic).
#pragma unroll
    for (int o = 16; o > 0; o >>= 1) {
        cc += __shfl_down_sync(0xFFFFFFFFu, cc, o);
        tp += __shfl_down_sync(0xFFFFFFFFu, tp, o);
    }
    if ((t & 31) == 0) {
        atomicAdd(&g_cc, cc);
        atomicAdd(&g_tp, tp);
    }
}

__global__ void cindex_fin_kernel(float* __restrict__ out) {
    // Match reference: int32 counts cast to float32, fp32 division.
    out[0] = (float)g_cc / (float)g_tp;
}

extern "C" void kernel_launch(void* const* d_in, const int* in_sizes, int n_in,
                              void* d_out, int out_size) {
    const float* y      = (const float*)d_in[0];
    const float* y_hat  = (const float*)d_in[1];
    const int*   status = (const int*)d_in[2];
    float*       out    = (float*)d_out;

    cindex_zero_kernel<<<1, 1>>>();
    cindex_prep_kernel<<<N_ELEM / THREADS, THREADS>>>(y, status);

    dim3 grid(N_ELEM / TJ, N_ELEM / TI);   // (64, 16)
    cindex_pair_kernel<<<grid, THREADS>>>(y, y_hat);

    cindex_fin_kernel<<<1, 1>>>(out);
}

// round 2
// speedup vs baseline: 1.0822x; 1.0822x over previous
#include <cuda_runtime.h>
#include <math_constants.h>

#define N_ELEM   16384
#define NTILE    64          // tiles of 256 sorted positions
#define TSZ      256
#define NBIN     16384       // histogram bins (14 bits of sortable key)
#define PBLOCKS  2080        // NTILE*(NTILE+1)/2 unordered tile pairs incl. diagonal
#define PTHREADS 64
#define IPT      4           // a-elements per thread (64*4 = 256 = TSZ)

// ---------------- device scratch (no allocations allowed) ----------------
__device__ float4       g_pack[N_ELEM];    // (y, ym, yh, yhm) in bucketed order
__device__ unsigned int g_hist[NBIN];
__device__ unsigned int g_binpos[NBIN];
__device__ unsigned int g_tminu[NTILE];
__device__ unsigned int g_tmaxu[NTILE];
__device__ unsigned int g_cc;
__device__ unsigned int g_tp;

// monotone float -> uint transform (order-preserving, -0 folded to +0)
__device__ __forceinline__ unsigned int sortable_u(float v) {
    unsigned int b = __float_as_uint(v);
    if (b == 0x80000000u) b = 0u;                       // -0 -> +0
    return (b & 0x80000000u) ? ~b : (b | 0x80000000u);
}

// ---------------- K0: zero everything ----------------
__global__ void k_zero() {
    int i = blockIdx.x * blockDim.x + threadIdx.x;
    if (i < NBIN) g_hist[i] = 0u;
    if (i < NTILE) { g_tminu[i] = 0xFFFFFFFFu; g_tmaxu[i] = 0u; }
    if (i == 0) { g_cc = 0u; g_tp = 0u; }
}

// ---------------- K1: histogram over y ----------------
__global__ void k_hist(const float* __restrict__ y) {
    int i = blockIdx.x * blockDim.x + threadIdx.x;
    unsigned int u = sortable_u(y[i]);
    atomicAdd(&g_hist[u >> 18], 1u);
}

// ---------------- K2: exclusive scan of 16384 bins (1 block, 1024 thr) ----------------
__global__ void k_scan() {
    __shared__ unsigned int part[1024];
    const int t = threadIdx.x;
    unsigned int loc[16];
    unsigned int sum = 0u;
#pragma unroll
    for (int k = 0; k < 16; k++) { loc[k] = g_hist[t * 16 + k]; sum += loc[k]; }
    part[t] = sum;
    __syncthreads();
    // Hillis-Steele inclusive scan over 1024 partials
    for (int off = 1; off < 1024; off <<= 1) {
        unsigned int v = (t >= off) ? part[t - off] : 0u;
        __syncthreads();
        part[t] += v;
        __syncthreads();
    }
    unsigned int running = part[t] - sum;  // exclusive prefix
#pragma unroll
    for (int k = 0; k < 16; k++) {
        g_binpos[t * 16 + k] = running;
        running += loc[k];
    }
}

// ---------------- K3: scatter into bucketed order + per-tile key min/max ----------------
__global__ void k_scatter(const float* __restrict__ y,
                          const float* __restrict__ yh,
                          const int* __restrict__ status) {
    int i = blockIdx.x * blockDim.x + threadIdx.x;
    float yv  = y[i];
    float yhv = yh[i];
    int   s   = status[i];
    unsigned int u = sortable_u(yv);
    unsigned int bin = u >> 18;
    unsigned int pos = atomicAdd(&g_binpos[bin], 1u);
    float ym  = (s == 1) ? yv  : CUDART_INF_F;
    float yhm = (s == 1) ? yhv : CUDART_INF_F;
    g_pack[pos] = make_float4(yv, ym, yhv, yhm);
    unsigned int tile = pos >> 8;
    atomicMin(&g_tminu[tile], u);
    atomicMax(&g_tmaxu[tile], u);
}

// ---------------- K4: pair kernel over unordered tile pairs ----------------
// Per unordered position pair {p<q}, exact contribution (s folded into ym/yhm):
//   cc += [y_q>=y_p & yh_q>=yhm_p] | [y_p>=y_q & yh_p>=yhm_q]
//   tp += [y_q>=ym_p]              | [y_p>=ym_q]
// Fast tile pairs (strict y separation, hi>lo): reverse terms are 0 and
// y_q>=y_p is always true -> cc += [yh_q>=yhm_p], tp += s_p (block closed form).
__global__ __launch_bounds__(PTHREADS)
void k_pairs() {
    // decode (tH, tL), tL <= tH, from linear block id
    int rem = blockIdx.x, tH = 0;
    while (rem > tH) { rem -= (tH + 1); tH++; }
    const int tL = rem;

    __shared__ float4 sp[TSZ];

    const int t = threadIdx.x;

    // load A-tile (high tile) elements into registers
    float4 ap[IPT];
    int    qpos[IPT];
#pragma unroll
    for (int k = 0; k < IPT; k++) {
        int idx = tH * TSZ + t + k * PTHREADS;
        qpos[k] = idx;
        ap[k]   = g_pack[idx];
    }

    // load B-tile (low tile) into shared; count its s=1 elements
    unsigned int cb = 0u;
#pragma unroll
    for (int k = 0; k < IPT; k++) {
        int j = t + k * PTHREADS;
        float4 v = g_pack[tL * TSZ + j];
        sp[j] = v;
        cb += (v.w < CUDART_INF_F) ? 1u : 0u;   // yhm finite <=> s==1
    }
    __syncthreads();

    const bool fast = (tH != tL) && (g_tminu[tH] > g_tmaxu[tL]);

    unsigned int cc = 0u, tp = 0u;

    if (fast) {
#pragma unroll 4
        for (int p = 0; p < TSZ; p++) {
            const float yhmp = sp[p].w;
#pragma unroll
            for (int k = 0; k < IPT; k++)
                cc += (unsigned int)(ap[k].z >= yhmp);
        }
        // tp contribution: 256 * (# s=1 in B-tile), accumulated per warp
#pragma unroll
        for (int o = 16; o > 0; o >>= 1)
            cb += __shfl_down_sync(0xFFFFFFFFu, cb, o);
        if ((t & 31) == 0) atomicAdd(&g_tp, cb * (unsigned int)TSZ);
    } else {
        for (int p = 0; p < TSZ; p++) {
            const float4 bp  = sp[p];
            const int    pp  = tL * TSZ + p;
#pragma unroll
            for (int k = 0; k < IPT; k++) {
                const bool m  = (qpos[k] > pp);
                const bool f1 = m && (ap[k].x >= bp.x) && (ap[k].z >= bp.w);
                const bool f2 = m && (bp.x >= ap[k].x) && (bp.z >= ap[k].w);
                const bool g1 = m && (ap[k].x >= bp.y);
                const bool g2 = m && (bp.x >= ap[k].y);
                cc += (unsigned int)(f1 | f2);
                tp += (unsigned int)(g1 | g2);
            }
        }
#pragma unroll
        for (int o = 16; o > 0; o >>= 1)
            tp += __shfl_down_sync(0xFFFFFFFFu, tp, o);
        if ((t & 31) == 0) atomicAdd(&g_tp, tp);
    }

#pragma unroll
    for (int o = 16; o > 0; o >>= 1)
        cc += __shfl_down_sync(0xFFFFFFFFu, cc, o);
    if ((t & 31) == 0) atomicAdd(&g_cc, cc);
}

// ---------------- K5: finalize ----------------
__global__ void k_fin(float* __restrict__ out) {
    out[0] = (float)g_cc / (float)g_tp;
}

extern "C" void kernel_launch(void* const* d_in, const int* in_sizes, int n_in,
                              void* d_out, int out_size) {
    const float* y      = (const float*)d_in[0];
    const float* y_hat  = (const float*)d_in[1];
    const int*   status = (const int*)d_in[2];
    float*       out    = (float*)d_out;

    k_zero<<<NBIN / 256, 256>>>();
    k_hist<<<N_ELEM / 256, 256>>>(y);
    k_scan<<<1, 1024>>>();
    k_scatter<<<N_ELEM / 256, 256>>>(y, y_hat, status);
    k_pairs<<<PBLOCKS, PTHREADS>>>();
    k_fin<<<1, 1>>>(out);
}